// round 6
// baseline (speedup 1.0000x reference)
#include <cuda_runtime.h>
#include <cuda_fp16.h>
#include <stdint.h>
#include <math.h>

// ---------------- problem dims ----------------
#define B_   4096
#define H_   512
#define LH_  1024
#define E_   2048
#define NG_  4096   // 4*LH

// ---------------- GEMM tiling ----------------
#define BM 128
#define BN 128
#define BK 32
#define SROW 40                    // halves per smem row (80 B): conflict-free ldmatrix
#define STAGE_B (128 * SROW * 2)   // bytes per tile stage (A or B) = 10240
#define NSTAGE 3
#define SMEM_BYTES (2 * NSTAGE * STAGE_B)   // 61440

// ---------------- scratch (static device memory) ----------------
__device__ __half g_xh  [(size_t)B_ * E_];     // embedded input, fp16
__device__ __half g_ench[(size_t)B_ * 2 * H_]; // encoder state, fp16
__device__ float  g_hc0 [(size_t)B_ * LH_];    // bridge output dup, fp32 (c_prev)
__device__ __half g_hc0h[(size_t)B_ * LH_];    // bridge output dup, fp16 (GEMM operand)
__device__ __half g_h1h [(size_t)B_ * LH_];    // layer-1 hidden, fp16
__device__ __half g_wh  [(size_t)20 * 1024 * 1024]; // fp16 perm weights: ih1(8M) hh1(4M) ih2(4M) hh2(4M)
__device__ __half g_bwh [(size_t)H_ * 2 * H_]; // fp16 bridge_W
__device__ float  g_b1[NG_];                   // permuted b_ih1 + b_hh1
__device__ float  g_b2[NG_];                   // permuted b_ih2 + b_hh2

// ---------------- helpers ----------------
__device__ __forceinline__ uint32_t smem_u32(const void* p)
{
    uint32_t a;
    asm("{ .reg .u64 t; cvta.to.shared.u64 t, %1; cvt.u32.u64 %0, t; }" : "=r"(a) : "l"(p));
    return a;
}

__device__ __forceinline__ void cp16(uint32_t sa, const void* g)
{
    asm volatile("cp.async.cg.shared.global [%0], [%1], 16;" :: "r"(sa), "l"(g));
}

__device__ __forceinline__ void ldsm4(uint32_t* r, uint32_t addr)
{
    asm volatile("ldmatrix.sync.aligned.m8n8.x4.shared.b16 {%0,%1,%2,%3}, [%4];"
                 : "=r"(r[0]), "=r"(r[1]), "=r"(r[2]), "=r"(r[3]) : "r"(addr));
}

__device__ __forceinline__ float sigf(float x) { return 1.0f / (1.0f + expf(-x)); }

// gate-interleave permutation: old weight row r (gate = r/1024, unit n = r%1024)
// -> new row: group = n/4, t = n%4; within = gate<2 ? 2t+gate : 8+2t+(gate&1)
__device__ __forceinline__ int perm_row(int r)
{
    int gate = r >> 10;
    int n = r & 1023;
    int t = n & 3, group = n >> 2;
    int within = (gate < 2) ? (2 * t + gate) : (8 + 2 * t + (gate & 1));
    return (group << 4) + within;
}

// ---------------- elementwise pre-pass kernels ----------------
__global__ void f2h_kernel(const float4* __restrict__ src, uint2* __restrict__ dst)
{
    int i = blockIdx.x * blockDim.x + threadIdx.x;
    float4 v = src[i];
    __half2 lo = __floats2half2_rn(v.x, v.y);
    __half2 hi = __floats2half2_rn(v.z, v.w);
    uint2 o;
    o.x = *(const uint32_t*)&lo;
    o.y = *(const uint32_t*)&hi;
    dst[i] = o;
}

// convert + permute rows of a [NG, K] weight matrix (K/4 given as shift)
__global__ void f2h_perm_kernel(const float4* __restrict__ src, uint2* __restrict__ dst,
                                int k4shift)
{
    int i = blockIdx.x * blockDim.x + threadIdx.x;   // over NG * K/4
    int row = i >> k4shift;
    int c4  = i & ((1 << k4shift) - 1);
    float4 v = src[i];
    __half2 lo = __floats2half2_rn(v.x, v.y);
    __half2 hi = __floats2half2_rn(v.z, v.w);
    uint2 o;
    o.x = *(const uint32_t*)&lo;
    o.y = *(const uint32_t*)&hi;
    dst[((size_t)perm_row(row) << k4shift) + c4] = o;
}

__global__ void bias_perm_kernel(const float* __restrict__ a, const float* __restrict__ b,
                                 float* __restrict__ o)
{
    int i = blockIdx.x * blockDim.x + threadIdx.x;
    o[perm_row(i)] = a[i] + b[i];
}

__global__ void gather_kernel(const int* __restrict__ input,
                              const float4* __restrict__ emb,
                              uint2* __restrict__ xh)
{
    int idx = blockIdx.x * blockDim.x + threadIdx.x;   // over B * (E/4)
    int b = idx >> 9;            // E/4 = 512
    int j = idx & 511;
    int tok = input[b];
    float4 v = emb[(size_t)tok * 512 + j];
    __half2 lo = __floats2half2_rn(v.x, v.y);
    __half2 hi = __floats2half2_rn(v.z, v.w);
    uint2 o;
    o.x = *(const uint32_t*)&lo;
    o.y = *(const uint32_t*)&hi;
    xh[idx] = o;
}

// ---------------- fp16 mma.sync GEMM with fused epilogues ----------------
// C[M,N] = A1 @ W1^T + A2 @ W2^T + bias   (half operands K-major, fp32 accum)
// epi=1: bridge duplicate (N=512): outF1 fp32 and outH fp16 both get v at
//        [row*1024 + col] and [row*1024 + col + 512]
// epi=2: fused LSTM activation (N=4096, gate-interleaved weights):
//        h = sigmoid(o) * tanh(sigmoid(f)*cprev + sigmoid(i)*tanh(g))
//        h -> outF1[row*1024+u], optionally outF2, optionally outH (fp16)
__global__ void __launch_bounds__(128, 2)
gemm_fp16_kernel(const __half* __restrict__ A1, const __half* __restrict__ W1, int K1,
                 const __half* __restrict__ A2, const __half* __restrict__ W2, int K2,
                 const float* __restrict__ bias,
                 const float* __restrict__ cprev,
                 float* __restrict__ outF1, float* __restrict__ outF2,
                 __half* __restrict__ outH, int N, int epi)
{
    extern __shared__ __half smem[];
    const uint32_t sbase = smem_u32(smem);
    const int tid  = threadIdx.x;
    const int lane = tid & 31;
    const int warp = tid >> 5;
    const int wm = (warp & 1) * 64;
    const int wn = (warp >> 1) * 64;
    const int bm = blockIdx.y * BM;
    const int bn = blockIdx.x * BN;

    float acc[4][8][4];
    #pragma unroll
    for (int mi = 0; mi < 4; ++mi)
        #pragma unroll
        for (int ni = 0; ni < 8; ++ni)
            #pragma unroll
            for (int r = 0; r < 4; ++r)
                acc[mi][ni][r] = 0.0f;

    const int nk = (K1 + K2) / BK;

    auto load_tile = [&](int kt, int s) {
        int kk = kt * BK;
        const __half* As; const __half* Bs; int ld;
        if (kk < K1) { As = A1 + kk; Bs = W1 + kk; ld = K1; }
        else         { As = A2 + (kk - K1); Bs = W2 + (kk - K1); ld = K2; }
        uint32_t a_dst = sbase + s * STAGE_B;
        uint32_t b_dst = sbase + NSTAGE * STAGE_B + s * STAGE_B;
        #pragma unroll
        for (int it = 0; it < 4; ++it) {
            int idx = tid + it * 128;       // 0..511
            int row = idx >> 2;             // 0..127
            int c8  = (idx & 3) << 3;       // half offset 0,8,16,24
            cp16(a_dst + (row * SROW + c8) * 2, As + (size_t)(bm + row) * ld + c8);
            cp16(b_dst + (row * SROW + c8) * 2, Bs + (size_t)(bn + row) * ld + c8);
        }
        asm volatile("cp.async.commit_group;");
    };

    load_tile(0, 0);
    load_tile(1, 1);

    // per-lane ldmatrix base addresses (bytes)
    const uint32_t base_a = sbase +
        (((wm + (lane & 15)) * SROW + ((lane >> 4) << 3)) << 1);
    const uint32_t base_b = sbase + NSTAGE * STAGE_B +
        (((wn + (lane & 7) + ((lane >> 4) << 3)) * SROW + (((lane >> 3) & 1) << 3)) << 1);

    for (int kt = 0; kt < nk; ++kt) {
        if (kt + 1 < nk) asm volatile("cp.async.wait_group 1;");
        else             asm volatile("cp.async.wait_group 0;");
        __syncthreads();
        if (kt + 2 < nk) load_tile(kt + 2, (kt + 2) % NSTAGE);

        const int s = kt % NSTAGE;
        const uint32_t sa = base_a + s * STAGE_B;
        const uint32_t sb = base_b + s * STAGE_B;

        // prefetch ALL fragments for this K-tile, then run MMAs
        uint32_t a[2][4][4], b[2][4][4];
        #pragma unroll
        for (int ks = 0; ks < 2; ++ks) {
            #pragma unroll
            for (int mi = 0; mi < 4; ++mi)
                ldsm4(a[ks][mi], sa + ((mi * 16 * SROW + ks * 16) << 1));
            #pragma unroll
            for (int g = 0; g < 4; ++g)
                ldsm4(b[ks][g], sb + ((g * 16 * SROW + ks * 16) << 1));
        }
        #pragma unroll
        for (int ks = 0; ks < 2; ++ks)
            #pragma unroll
            for (int mi = 0; mi < 4; ++mi)
                #pragma unroll
                for (int ni = 0; ni < 8; ++ni) {
                    float* d = acc[mi][ni];
                    uint32_t b0 = b[ks][ni >> 1][(ni & 1) * 2];
                    uint32_t b1 = b[ks][ni >> 1][(ni & 1) * 2 + 1];
                    asm volatile(
                        "mma.sync.aligned.m16n8k16.row.col.f32.f16.f16.f32 "
                        "{%0,%1,%2,%3}, {%4,%5,%6,%7}, {%8,%9}, {%0,%1,%2,%3};"
                        : "+f"(d[0]), "+f"(d[1]), "+f"(d[2]), "+f"(d[3])
                        : "r"(a[ks][mi][0]), "r"(a[ks][mi][1]),
                          "r"(a[ks][mi][2]), "r"(a[ks][mi][3]),
                          "r"(b0), "r"(b1));
                }
    }

    if (epi == 1) {
        // bridge duplicate epilogue
        #pragma unroll
        for (int mi = 0; mi < 4; ++mi) {
            int r0 = bm + wm + mi * 16 + (lane >> 2);
            #pragma unroll
            for (int ni = 0; ni < 8; ++ni) {
                int c0 = bn + wn + ni * 8 + ((lane & 3) << 1);
                float bv0 = bias[c0], bv1 = bias[c0 + 1];
                float v00 = acc[mi][ni][0] + bv0;
                float v01 = acc[mi][ni][1] + bv1;
                float v10 = acc[mi][ni][2] + bv0;
                float v11 = acc[mi][ni][3] + bv1;
                size_t o0 = (size_t)r0 * LH_ + c0;
                size_t o1 = (size_t)(r0 + 8) * LH_ + c0;
                __half2 h0 = __floats2half2_rn(v00, v01);
                __half2 h1 = __floats2half2_rn(v10, v11);
                *(float2*)(outF1 + o0)      = make_float2(v00, v01);
                *(float2*)(outF1 + o0 + H_) = make_float2(v00, v01);
                *(float2*)(outF1 + o1)      = make_float2(v10, v11);
                *(float2*)(outF1 + o1 + H_) = make_float2(v10, v11);
                *(__half2*)(outH + o0)      = h0;
                *(__half2*)(outH + o0 + H_) = h0;
                *(__half2*)(outH + o1)      = h1;
                *(__half2*)(outH + o1 + H_) = h1;
            }
        }
    } else {
        // fused LSTM activation epilogue (gate-interleaved columns)
        const int t = lane & 3;
        #pragma unroll
        for (int a2 = 0; a2 < 4; ++a2) {
            int cb = bn + wn + a2 * 16 + (t << 1);
            float bi = bias[cb],     bf = bias[cb + 1];
            float bg = bias[cb + 8], bo = bias[cb + 9];
            int u = ((bn + wn + a2 * 16) >> 2) + t;     // hidden unit 0..1023
            #pragma unroll
            for (int mi = 0; mi < 4; ++mi) {
                int r0 = bm + wm + mi * 16 + (lane >> 2);
                // row r0
                {
                    float gi = sigf(acc[mi][2 * a2][0] + bi);
                    float gf = sigf(acc[mi][2 * a2][1] + bf);
                    float gg = tanhf(acc[mi][2 * a2 + 1][0] + bg);
                    float go = sigf(acc[mi][2 * a2 + 1][1] + bo);
                    size_t ix = (size_t)r0 * LH_ + u;
                    float c = gf * cprev[ix] + gi * gg;
                    float h = go * tanhf(c);
                    outF1[ix] = h;
                    if (outF2) outF2[ix] = h;
                    if (outH)  outH[ix] = __float2half_rn(h);
                }
                // row r0+8
                {
                    float gi = sigf(acc[mi][2 * a2][2] + bi);
                    float gf = sigf(acc[mi][2 * a2][3] + bf);
                    float gg = tanhf(acc[mi][2 * a2 + 1][2] + bg);
                    float go = sigf(acc[mi][2 * a2 + 1][3] + bo);
                    size_t ix = (size_t)(r0 + 8) * LH_ + u;
                    float c = gf * cprev[ix] + gi * gg;
                    float h = go * tanhf(c);
                    outF1[ix] = h;
                    if (outF2) outF2[ix] = h;
                    if (outH)  outH[ix] = __float2half_rn(h);
                }
            }
        }
    }
}

// ---------------- launch ----------------
extern "C" void kernel_launch(void* const* d_in, const int* in_sizes, int n_in,
                              void* d_out, int out_size)
{
    const int*   input    = (const int*)d_in[0];
    const float* enc      = (const float*)d_in[1];
    const float* bridge_W = (const float*)d_in[2];
    const float* bridge_b = (const float*)d_in[3];
    const float* emb      = (const float*)d_in[4];
    const float* w_ih1    = (const float*)d_in[5];
    const float* w_hh1    = (const float*)d_in[6];
    const float* b_ih1    = (const float*)d_in[7];
    const float* b_hh1    = (const float*)d_in[8];
    const float* w_ih2    = (const float*)d_in[9];
    const float* w_hh2    = (const float*)d_in[10];
    const float* b_ih2    = (const float*)d_in[11];
    const float* b_hh2    = (const float*)d_in[12];
    float* out = (float*)d_out;

    __half *xh, *ench, *hc0h, *h1h, *wh, *bwh;
    float *hc0, *b1, *b2;
    cudaGetSymbolAddress((void**)&xh,    g_xh);
    cudaGetSymbolAddress((void**)&ench,  g_ench);
    cudaGetSymbolAddress((void**)&hc0,   g_hc0);
    cudaGetSymbolAddress((void**)&hc0h,  g_hc0h);
    cudaGetSymbolAddress((void**)&h1h,   g_h1h);
    cudaGetSymbolAddress((void**)&wh,    g_wh);
    cudaGetSymbolAddress((void**)&bwh,   g_bwh);
    cudaGetSymbolAddress((void**)&b1,    g_b1);
    cudaGetSymbolAddress((void**)&b2,    g_b2);

    __half* w_ih1h = wh;
    __half* w_hh1h = wh + (size_t)8  * 1024 * 1024;
    __half* w_ih2h = wh + (size_t)12 * 1024 * 1024;
    __half* w_hh2h = wh + (size_t)16 * 1024 * 1024;

    cudaFuncSetAttribute(gemm_fp16_kernel,
                         cudaFuncAttributeMaxDynamicSharedMemorySize, SMEM_BYTES);

    const size_t BLH = (size_t)B_ * LH_;

    // 0) fp16 conversions (+ gate-interleave permutation for LSTM weights/biases)
    f2h_perm_kernel<<<((size_t)NG_ * E_  / 4) / 256, 256>>>((const float4*)w_ih1, (uint2*)w_ih1h, 9);
    f2h_perm_kernel<<<((size_t)NG_ * LH_ / 4) / 256, 256>>>((const float4*)w_hh1, (uint2*)w_hh1h, 8);
    f2h_perm_kernel<<<((size_t)NG_ * LH_ / 4) / 256, 256>>>((const float4*)w_ih2, (uint2*)w_ih2h, 8);
    f2h_perm_kernel<<<((size_t)NG_ * LH_ / 4) / 256, 256>>>((const float4*)w_hh2, (uint2*)w_hh2h, 8);
    f2h_kernel<<<((size_t)H_ * 2 * H_ / 4) / 256, 256>>>((const float4*)bridge_W, (uint2*)bwh);
    f2h_kernel<<<((size_t)B_ * 2 * H_ / 4) / 256, 256>>>((const float4*)enc, (uint2*)ench);
    bias_perm_kernel<<<NG_ / 256, 256>>>(b_ih1, b_hh1, b1);
    bias_perm_kernel<<<NG_ / 256, 256>>>(b_ih2, b_hh2, b2);

    // 1) x = fp16(emb[input])
    gather_kernel<<<(B_ * (E_ / 4)) / 256, 256>>>(input, (const float4*)emb, (uint2*)xh);

    // 2) bridge: hc0 / hc0h = dup(enc @ bridge_W^T + b)   (M=B, N=512, K=1024)
    gemm_fp16_kernel<<<dim3(H_ / BN, B_ / BM), 128, SMEM_BYTES>>>(
        ench, bwh, 2 * H_, ench, bwh, 0,
        bridge_b, nullptr, hc0, nullptr, hc0h, H_, 1);

    // 3) layer 1: gates1 GEMM + fused act -> h1 (fp16) + hidden_state[0] (fp32)
    gemm_fp16_kernel<<<dim3(NG_ / BN, B_ / BM), 128, SMEM_BYTES>>>(
        xh, w_ih1h, E_, hc0h, w_hh1h, LH_,
        b1, hc0, out + BLH, nullptr, h1h, NG_, 2);

    // 4) layer 2: gates2 GEMM + fused act -> output + hidden_state[1] (fp32)
    gemm_fp16_kernel<<<dim3(NG_ / BN, B_ / BM), 128, SMEM_BYTES>>>(
        h1h, w_ih2h, LH_, hc0h, w_hh2h, LH_,
        b2, hc0, out, out + 2 * BLH, nullptr, NG_, 2);
}

// round 7
// speedup vs baseline: 1.0655x; 1.0655x over previous
#include <cuda_runtime.h>
#include <cuda_fp16.h>
#include <stdint.h>
#include <math.h>

// ---------------- problem dims ----------------
#define B_   4096
#define H_   512
#define LH_  1024
#define E_   2048
#define NG_  4096   // 4*LH

// ---------------- GEMM tiling ----------------
#define BM 128
#define BN 128
#define BK 32
#define SROW 40                    // halves per smem row (80 B): conflict-free ldmatrix
#define STAGE_B (128 * SROW * 2)   // bytes per tile stage (A or B) = 10240
#define NSTAGE 3
#define SMEM_BYTES (2 * NSTAGE * STAGE_B)   // 61440

// ---------------- scratch (static device memory) ----------------
__device__ __half g_xh  [(size_t)B_ * E_];     // embedded input, fp16
__device__ __half g_ench[(size_t)B_ * 2 * H_]; // encoder state, fp16
__device__ float  g_hc0 [(size_t)B_ * LH_];    // bridge output dup, fp32 (c_prev)
__device__ __half g_hc0h[(size_t)B_ * LH_];    // bridge output dup, fp16 (GEMM operand)
__device__ __half g_h1h [(size_t)B_ * LH_];    // layer-1 hidden, fp16
__device__ __half g_wh  [(size_t)20 * 1024 * 1024]; // fp16 perm weights: ih1(8M) hh1(4M) ih2(4M) hh2(4M)
__device__ __half g_bwh [(size_t)H_ * 2 * H_]; // fp16 bridge_W
__device__ float  g_b1[NG_];                   // permuted b_ih1 + b_hh1
__device__ float  g_b2[NG_];                   // permuted b_ih2 + b_hh2

// ---------------- helpers ----------------
__device__ __forceinline__ uint32_t smem_u32(const void* p)
{
    uint32_t a;
    asm("{ .reg .u64 t; cvta.to.shared.u64 t, %1; cvt.u32.u64 %0, t; }" : "=r"(a) : "l"(p));
    return a;
}

__device__ __forceinline__ void cp16(uint32_t sa, const void* g)
{
    asm volatile("cp.async.cg.shared.global [%0], [%1], 16;" :: "r"(sa), "l"(g));
}

__device__ __forceinline__ void ldsm4(uint32_t* r, uint32_t addr)
{
    asm volatile("ldmatrix.sync.aligned.m8n8.x4.shared.b16 {%0,%1,%2,%3}, [%4];"
                 : "=r"(r[0]), "=r"(r[1]), "=r"(r[2]), "=r"(r[3]) : "r"(addr));
}

__device__ __forceinline__ float sigf(float x) { return 1.0f / (1.0f + expf(-x)); }

// gate-interleave permutation: old weight row r (gate = r/1024, unit n = r%1024)
// -> new row: group = n/4, t = n%4; within = gate<2 ? 2t+gate : 8+2t+(gate&1)
__device__ __forceinline__ int perm_row(int r)
{
    int gate = r >> 10;
    int n = r & 1023;
    int t = n & 3, group = n >> 2;
    int within = (gate < 2) ? (2 * t + gate) : (8 + 2 * t + (gate & 1));
    return (group << 4) + within;
}

// ---------------- elementwise pre-pass kernels ----------------
__global__ void f2h_kernel(const float4* __restrict__ src, uint2* __restrict__ dst)
{
    int i = blockIdx.x * blockDim.x + threadIdx.x;
    float4 v = src[i];
    __half2 lo = __floats2half2_rn(v.x, v.y);
    __half2 hi = __floats2half2_rn(v.z, v.w);
    uint2 o;
    o.x = *(const uint32_t*)&lo;
    o.y = *(const uint32_t*)&hi;
    dst[i] = o;
}

// convert + permute rows of a [NG, K] weight matrix (K/4 given as shift)
__global__ void f2h_perm_kernel(const float4* __restrict__ src, uint2* __restrict__ dst,
                                int k4shift)
{
    int i = blockIdx.x * blockDim.x + threadIdx.x;   // over NG * K/4
    int row = i >> k4shift;
    int c4  = i & ((1 << k4shift) - 1);
    float4 v = src[i];
    __half2 lo = __floats2half2_rn(v.x, v.y);
    __half2 hi = __floats2half2_rn(v.z, v.w);
    uint2 o;
    o.x = *(const uint32_t*)&lo;
    o.y = *(const uint32_t*)&hi;
    dst[((size_t)perm_row(row) << k4shift) + c4] = o;
}

__global__ void bias_perm_kernel(const float* __restrict__ a, const float* __restrict__ b,
                                 float* __restrict__ o)
{
    int i = blockIdx.x * blockDim.x + threadIdx.x;
    o[perm_row(i)] = a[i] + b[i];
}

__global__ void gather_kernel(const int* __restrict__ input,
                              const float4* __restrict__ emb,
                              uint2* __restrict__ xh)
{
    int idx = blockIdx.x * blockDim.x + threadIdx.x;   // over B * (E/4)
    int b = idx >> 9;            // E/4 = 512
    int j = idx & 511;
    int tok = input[b];
    float4 v = emb[(size_t)tok * 512 + j];
    __half2 lo = __floats2half2_rn(v.x, v.y);
    __half2 hi = __floats2half2_rn(v.z, v.w);
    uint2 o;
    o.x = *(const uint32_t*)&lo;
    o.y = *(const uint32_t*)&hi;
    xh[idx] = o;
}

// ---------------- fp16 mma.sync GEMM with fused epilogues ----------------
// 256 threads, 8 warps of 32x64 (4 along M, 2 along N); 3-stage cp.async; ldmatrix.
// C[M,N] = A1 @ W1^T + A2 @ W2^T + bias   (half operands K-major, fp32 accum)
// epi=1: bridge duplicate (N=512): outF1 fp32 and outH fp16 get v at
//        [row*1024 + col] and [row*1024 + col + 512]
// epi=2: fused LSTM activation (N=4096, gate-interleaved weights)
__global__ void __launch_bounds__(256, 2)
gemm_fp16_kernel(const __half* __restrict__ A1, const __half* __restrict__ W1, int K1,
                 const __half* __restrict__ A2, const __half* __restrict__ W2, int K2,
                 const float* __restrict__ bias,
                 const float* __restrict__ cprev,
                 float* __restrict__ outF1, float* __restrict__ outF2,
                 __half* __restrict__ outH, int N, int epi)
{
    extern __shared__ __half smem[];
    const uint32_t sbase = smem_u32(smem);
    const int tid  = threadIdx.x;
    const int lane = tid & 31;
    const int warp = tid >> 5;
    const int wm = (warp & 3) * 32;   // 4 warps along M, 32 rows each
    const int wn = (warp >> 2) * 64;  // 2 warps along N, 64 cols each
    const int bm = blockIdx.y * BM;
    const int bn = blockIdx.x * BN;

    float acc[2][8][4];
    #pragma unroll
    for (int mi = 0; mi < 2; ++mi)
        #pragma unroll
        for (int ni = 0; ni < 8; ++ni)
            #pragma unroll
            for (int r = 0; r < 4; ++r)
                acc[mi][ni][r] = 0.0f;

    const int nk = (K1 + K2) / BK;

    auto load_tile = [&](int kt, int s) {
        int kk = kt * BK;
        const __half* As; const __half* Bs; int ld;
        if (kk < K1) { As = A1 + kk; Bs = W1 + kk; ld = K1; }
        else         { As = A2 + (kk - K1); Bs = W2 + (kk - K1); ld = K2; }
        uint32_t a_dst = sbase + s * STAGE_B;
        uint32_t b_dst = sbase + NSTAGE * STAGE_B + s * STAGE_B;
        #pragma unroll
        for (int it = 0; it < 2; ++it) {
            int idx = tid + it * 256;       // 0..511
            int row = idx >> 2;             // 0..127
            int c8  = (idx & 3) << 3;       // half offset 0,8,16,24
            cp16(a_dst + (row * SROW + c8) * 2, As + (size_t)(bm + row) * ld + c8);
            cp16(b_dst + (row * SROW + c8) * 2, Bs + (size_t)(bn + row) * ld + c8);
        }
        asm volatile("cp.async.commit_group;");
    };

    load_tile(0, 0);
    load_tile(1, 1);

    // per-lane ldmatrix base addresses (bytes)
    const uint32_t base_a = sbase +
        (((wm + (lane & 15)) * SROW + ((lane >> 4) << 3)) << 1);
    const uint32_t base_b = sbase + NSTAGE * STAGE_B +
        (((wn + (lane & 7) + ((lane >> 4) << 3)) * SROW + (((lane >> 3) & 1) << 3)) << 1);

    for (int kt = 0; kt < nk; ++kt) {
        if (kt + 1 < nk) asm volatile("cp.async.wait_group 1;");
        else             asm volatile("cp.async.wait_group 0;");
        __syncthreads();
        if (kt + 2 < nk) load_tile(kt + 2, (kt + 2) % NSTAGE);

        const int s = kt % NSTAGE;
        const uint32_t sa = base_a + s * STAGE_B;
        const uint32_t sb = base_b + s * STAGE_B;

        #pragma unroll
        for (int ks = 0; ks < 2; ++ks) {            // two k16 halves of BK=32
            uint32_t a[2][4], b[4][4];
            #pragma unroll
            for (int mi = 0; mi < 2; ++mi)
                ldsm4(a[mi], sa + ((mi * 16 * SROW + ks * 16) << 1));
            #pragma unroll
            for (int g = 0; g < 4; ++g)
                ldsm4(b[g], sb + ((g * 16 * SROW + ks * 16) << 1));
            #pragma unroll
            for (int mi = 0; mi < 2; ++mi)
                #pragma unroll
                for (int ni = 0; ni < 8; ++ni) {
                    float* d = acc[mi][ni];
                    uint32_t b0 = b[ni >> 1][(ni & 1) * 2];
                    uint32_t b1 = b[ni >> 1][(ni & 1) * 2 + 1];
                    asm volatile(
                        "mma.sync.aligned.m16n8k16.row.col.f32.f16.f16.f32 "
                        "{%0,%1,%2,%3}, {%4,%5,%6,%7}, {%8,%9}, {%0,%1,%2,%3};"
                        : "+f"(d[0]), "+f"(d[1]), "+f"(d[2]), "+f"(d[3])
                        : "r"(a[mi][0]), "r"(a[mi][1]), "r"(a[mi][2]), "r"(a[mi][3]),
                          "r"(b0), "r"(b1));
                }
        }
    }

    if (epi == 1) {
        // bridge duplicate epilogue
        #pragma unroll
        for (int mi = 0; mi < 2; ++mi) {
            int r0 = bm + wm + mi * 16 + (lane >> 2);
            #pragma unroll
            for (int ni = 0; ni < 8; ++ni) {
                int c0 = bn + wn + ni * 8 + ((lane & 3) << 1);
                float bv0 = bias[c0], bv1 = bias[c0 + 1];
                float v00 = acc[mi][ni][0] + bv0;
                float v01 = acc[mi][ni][1] + bv1;
                float v10 = acc[mi][ni][2] + bv0;
                float v11 = acc[mi][ni][3] + bv1;
                size_t o0 = (size_t)r0 * LH_ + c0;
                size_t o1 = (size_t)(r0 + 8) * LH_ + c0;
                __half2 h0 = __floats2half2_rn(v00, v01);
                __half2 h1 = __floats2half2_rn(v10, v11);
                *(float2*)(outF1 + o0)      = make_float2(v00, v01);
                *(float2*)(outF1 + o0 + H_) = make_float2(v00, v01);
                *(float2*)(outF1 + o1)      = make_float2(v10, v11);
                *(float2*)(outF1 + o1 + H_) = make_float2(v10, v11);
                *(__half2*)(outH + o0)      = h0;
                *(__half2*)(outH + o0 + H_) = h0;
                *(__half2*)(outH + o1)      = h1;
                *(__half2*)(outH + o1 + H_) = h1;
            }
        }
    } else {
        // fused LSTM activation epilogue (gate-interleaved columns)
        const int t = lane & 3;
        #pragma unroll
        for (int a2 = 0; a2 < 4; ++a2) {
            int cb = bn + wn + a2 * 16 + (t << 1);
            float bi = bias[cb],     bf = bias[cb + 1];
            float bg = bias[cb + 8], bo = bias[cb + 9];
            int u = ((bn + wn + a2 * 16) >> 2) + t;     // hidden unit 0..1023
            #pragma unroll
            for (int mi = 0; mi < 2; ++mi) {
                int r0 = bm + wm + mi * 16 + (lane >> 2);
                {
                    float gi = sigf(acc[mi][2 * a2][0] + bi);
                    float gf = sigf(acc[mi][2 * a2][1] + bf);
                    float gg = tanhf(acc[mi][2 * a2 + 1][0] + bg);
                    float go = sigf(acc[mi][2 * a2 + 1][1] + bo);
                    size_t ix = (size_t)r0 * LH_ + u;
                    float c = gf * cprev[ix] + gi * gg;
                    float h = go * tanhf(c);
                    outF1[ix] = h;
                    if (outF2) outF2[ix] = h;
                    if (outH)  outH[ix] = __float2half_rn(h);
                }
                {
                    float gi = sigf(acc[mi][2 * a2][2] + bi);
                    float gf = sigf(acc[mi][2 * a2][3] + bf);
                    float gg = tanhf(acc[mi][2 * a2 + 1][2] + bg);
                    float go = sigf(acc[mi][2 * a2 + 1][3] + bo);
                    size_t ix = (size_t)(r0 + 8) * LH_ + u;
                    float c = gf * cprev[ix] + gi * gg;
                    float h = go * tanhf(c);
                    outF1[ix] = h;
                    if (outF2) outF2[ix] = h;
                    if (outH)  outH[ix] = __float2half_rn(h);
                }
            }
        }
    }
}

// ---------------- launch ----------------
extern "C" void kernel_launch(void* const* d_in, const int* in_sizes, int n_in,
                              void* d_out, int out_size)
{
    const int*   input    = (const int*)d_in[0];
    const float* enc      = (const float*)d_in[1];
    const float* bridge_W = (const float*)d_in[2];
    const float* bridge_b = (const float*)d_in[3];
    const float* emb      = (const float*)d_in[4];
    const float* w_ih1    = (const float*)d_in[5];
    const float* w_hh1    = (const float*)d_in[6];
    const float* b_ih1    = (const float*)d_in[7];
    const float* b_hh1    = (const float*)d_in[8];
    const float* w_ih2    = (const float*)d_in[9];
    const float* w_hh2    = (const float*)d_in[10];
    const float* b_ih2    = (const float*)d_in[11];
    const float* b_hh2    = (const float*)d_in[12];
    float* out = (float*)d_out;

    __half *xh, *ench, *hc0h, *h1h, *wh, *bwh;
    float *hc0, *b1, *b2;
    cudaGetSymbolAddress((void**)&xh,    g_xh);
    cudaGetSymbolAddress((void**)&ench,  g_ench);
    cudaGetSymbolAddress((void**)&hc0,   g_hc0);
    cudaGetSymbolAddress((void**)&hc0h,  g_hc0h);
    cudaGetSymbolAddress((void**)&h1h,   g_h1h);
    cudaGetSymbolAddress((void**)&wh,    g_wh);
    cudaGetSymbolAddress((void**)&bwh,   g_bwh);
    cudaGetSymbolAddress((void**)&b1,    g_b1);
    cudaGetSymbolAddress((void**)&b2,    g_b2);

    __half* w_ih1h = wh;
    __half* w_hh1h = wh + (size_t)8  * 1024 * 1024;
    __half* w_ih2h = wh + (size_t)12 * 1024 * 1024;
    __half* w_hh2h = wh + (size_t)16 * 1024 * 1024;

    cudaFuncSetAttribute(gemm_fp16_kernel,
                         cudaFuncAttributeMaxDynamicSharedMemorySize, SMEM_BYTES);

    const size_t BLH = (size_t)B_ * LH_;

    // 0) fp16 conversions (+ gate-interleave permutation for LSTM weights/biases)
    f2h_perm_kernel<<<((size_t)NG_ * E_  / 4) / 256, 256>>>((const float4*)w_ih1, (uint2*)w_ih1h, 9);
    f2h_perm_kernel<<<((size_t)NG_ * LH_ / 4) / 256, 256>>>((const float4*)w_hh1, (uint2*)w_hh1h, 8);
    f2h_perm_kernel<<<((size_t)NG_ * LH_ / 4) / 256, 256>>>((const float4*)w_ih2, (uint2*)w_ih2h, 8);
    f2h_perm_kernel<<<((size_t)NG_ * LH_ / 4) / 256, 256>>>((const float4*)w_hh2, (uint2*)w_hh2h, 8);
    f2h_kernel<<<((size_t)H_ * 2 * H_ / 4) / 256, 256>>>((const float4*)bridge_W, (uint2*)bwh);
    f2h_kernel<<<((size_t)B_ * 2 * H_ / 4) / 256, 256>>>((const float4*)enc, (uint2*)ench);
    bias_perm_kernel<<<NG_ / 256, 256>>>(b_ih1, b_hh1, b1);
    bias_perm_kernel<<<NG_ / 256, 256>>>(b_ih2, b_hh2, b2);

    // 1) x = fp16(emb[input])
    gather_kernel<<<(B_ * (E_ / 4)) / 256, 256>>>(input, (const float4*)emb, (uint2*)xh);

    // 2) bridge: hc0 / hc0h = dup(enc @ bridge_W^T + b)   (M=B, N=512, K=1024)
    gemm_fp16_kernel<<<dim3(H_ / BN, B_ / BM), 256, SMEM_BYTES>>>(
        ench, bwh, 2 * H_, ench, bwh, 0,
        bridge_b, nullptr, hc0, nullptr, hc0h, H_, 1);

    // 3) layer 1: gates1 GEMM + fused act -> h1 (fp16) + hidden_state[0] (fp32)
    gemm_fp16_kernel<<<dim3(NG_ / BN, B_ / BM), 256, SMEM_BYTES>>>(
        xh, w_ih1h, E_, hc0h, w_hh1h, LH_,
        b1, hc0, out + BLH, nullptr, h1h, NG_, 2);

    // 4) layer 2: gates2 GEMM + fused act -> output + hidden_state[1] (fp32)
    gemm_fp16_kernel<<<dim3(NG_ / BN, B_ / BM), 256, SMEM_BYTES>>>(
        h1h, w_ih2h, LH_, hc0h, w_hh2h, LH_,
        b2, hc0, out, out + 2 * BLH, nullptr, NG_, 2);
}